// round 4
// baseline (speedup 1.0000x reference)
#include <cuda_runtime.h>
#include <cstdint>

#define B 64
#define T 50
#define D 512
#define H 1024
#define V 32000
#define G3 3072   // 3*H

// ---------------- scratch (no allocations allowed) ----------------
__device__ float g_h[B * H];
__device__ float g_gi[B * G3];
__device__ float g_gh[B * G3];
__device__ unsigned long long g_packed[B];

// ---------------- packed f32x2 helpers (sm_100a) ----------------
__device__ __forceinline__ void fma2(unsigned long long& d, unsigned long long a, unsigned long long b) {
    asm("fma.rn.f32x2 %0, %1, %2, %0;" : "+l"(d) : "l"(a), "l"(b));
}
__device__ __forceinline__ unsigned long long pack2(float x, float y) {
    unsigned long long r; asm("mov.b64 %0, {%1, %2};" : "=l"(r) : "f"(x), "f"(y)); return r;
}
__device__ __forceinline__ float2 unpack2(unsigned long long v) {
    float2 r; asm("mov.b64 {%0, %1}, %2;" : "=f"(r.x), "=f"(r.y) : "l"(v)); return r;
}

// ---------------- threefry2x32 (exact JAX rotation/key schedule) ----------------
__device__ __forceinline__ void tf2x32(uint32_t k0, uint32_t k1, uint32_t x0, uint32_t x1,
                                       uint32_t& o0, uint32_t& o1) {
    uint32_t ks2 = k0 ^ k1 ^ 0x1BD11BDAu;
    x0 += k0; x1 += k1;
#define RND(r) { x0 += x1; x1 = __funnelshift_l(x1, x1, (r)); x1 ^= x0; }
    RND(13) RND(15) RND(26) RND(6)   x0 += k1;  x1 += ks2 + 1u;
    RND(17) RND(29) RND(16) RND(24)  x0 += ks2; x1 += k0  + 2u;
    RND(13) RND(15) RND(26) RND(6)   x0 += k0;  x1 += k1  + 3u;
    RND(17) RND(29) RND(16) RND(24)  x0 += k1;  x1 += ks2 + 4u;
    RND(13) RND(15) RND(26) RND(6)   x0 += ks2; x1 += k0  + 5u;
#undef RND
    o0 = x0; o1 = x1;
}

static inline uint32_t h_rotl(uint32_t v, int d) { return (v << d) | (v >> (32 - d)); }
static void tf2x32_host(uint32_t k0, uint32_t k1, uint32_t x0, uint32_t x1,
                        uint32_t* o0, uint32_t* o1) {
    uint32_t ks2 = k0 ^ k1 ^ 0x1BD11BDAu;
    const int rA[4] = {13, 15, 26, 6}, rB[4] = {17, 29, 16, 24};
    x0 += k0; x1 += k1;
    for (int i = 0; i < 4; i++) { x0 += x1; x1 = h_rotl(x1, rA[i]); x1 ^= x0; }
    x0 += k1;  x1 += ks2 + 1u;
    for (int i = 0; i < 4; i++) { x0 += x1; x1 = h_rotl(x1, rB[i]); x1 ^= x0; }
    x0 += ks2; x1 += k0 + 2u;
    for (int i = 0; i < 4; i++) { x0 += x1; x1 = h_rotl(x1, rA[i]); x1 ^= x0; }
    x0 += k0;  x1 += k1 + 3u;
    for (int i = 0; i < 4; i++) { x0 += x1; x1 = h_rotl(x1, rB[i]); x1 ^= x0; }
    x0 += k1;  x1 += ks2 + 4u;
    for (int i = 0; i < 4; i++) { x0 += x1; x1 = h_rotl(x1, rA[i]); x1 ^= x0; }
    x0 += ks2; x1 += k0 + 5u;
    *o0 = x0; *o1 = x1;
}

// ---------------- GRU gemm: gi = x@Wih^T + b_ih ; gh = h@Whh^T + b_hh ----------------
// Grid 96 blocks x 256 threads. Block tile: 64 b x 32 g rows, K = 512(x) + 1024(h).
// Also: block 0 writes out the sampled indices of step t-1 (read from g_packed).
__global__ void __launch_bounds__(256) gru_gemm_kernel(
    int t, const float* __restrict__ seq_emb, const float* __restrict__ emb,
    const float* __restrict__ Wih, const float* __restrict__ Whh,
    const float* __restrict__ bih, const float* __restrict__ bhh,
    const int* __restrict__ eosp, float* __restrict__ out)
{
    __shared__ float sA[64][68];
    __shared__ float sW[64][36];
    __shared__ int sIdx[B];
    int tid = threadIdx.x;
    int g0 = blockIdx.x * 32;

    if (tid < B) {
        int idx;
        if (t == 0) idx = eosp[0];
        else idx = (int)(0x7FFFFFFFu - (unsigned)(g_packed[tid] & 0xFFFFFFFFull));
        sIdx[tid] = idx;
        if (blockIdx.x == 0 && t > 0) out[(t - 1) * B + tid] = (float)idx;
    }
    __syncthreads();

    const float* hin = (t == 0) ? seq_emb : g_h;

    // acc pairs over batch: accI2[g(2)][bpair(2)], b = b0 + 2*p + {0,1}
    unsigned long long accI2[2][2] = {{0ull,0ull},{0ull,0ull}};
    unsigned long long accH2[2][2] = {{0ull,0ull},{0ull,0ull}};
    int gl0 = (tid & 15) * 2;
    int b0  = (tid >> 4) * 4;

    for (int c = 0; c < 24; c++) {
        int kb = c * 64;
        #pragma unroll
        for (int i = 0; i < 16; i++) {
            int e = tid + i * 256;
            int b = e >> 6, kk = e & 63;
            int kg = kb + kk;
            float v;
            if (kg < 512) v = emb[(size_t)sIdx[b] * D + kg];
            else          v = hin[b * H + (kg - 512)];
            sA[kk][b] = v;
        }
        #pragma unroll
        for (int i = 0; i < 8; i++) {
            int e = tid + i * 256;
            int gl = e >> 6, kk = e & 63;
            int g = g0 + gl;
            int kg = kb + kk;
            float v;
            if (kg < 512) v = Wih[(size_t)g * D + kg];
            else          v = Whh[(size_t)g * H + (kg - 512)];
            sW[kk][gl] = v;
        }
        __syncthreads();
        if (c < 8) {
            #pragma unroll
            for (int kk = 0; kk < 64; kk++) {
                ulonglong2 a2 = *(const ulonglong2*)&sA[kk][b0];
                float2 w = *(const float2*)&sW[kk][gl0];
                unsigned long long w0 = pack2(w.x, w.x);
                unsigned long long w1 = pack2(w.y, w.y);
                fma2(accI2[0][0], a2.x, w0); fma2(accI2[0][1], a2.y, w0);
                fma2(accI2[1][0], a2.x, w1); fma2(accI2[1][1], a2.y, w1);
            }
        } else {
            #pragma unroll
            for (int kk = 0; kk < 64; kk++) {
                ulonglong2 a2 = *(const ulonglong2*)&sA[kk][b0];
                float2 w = *(const float2*)&sW[kk][gl0];
                unsigned long long w0 = pack2(w.x, w.x);
                unsigned long long w1 = pack2(w.y, w.y);
                fma2(accH2[0][0], a2.x, w0); fma2(accH2[0][1], a2.y, w0);
                fma2(accH2[1][0], a2.x, w1); fma2(accH2[1][1], a2.y, w1);
            }
        }
        __syncthreads();
    }

    #pragma unroll
    for (int q = 0; q < 2; q++) {
        int g = g0 + gl0 + q;
        float bi = bih[g], bh = bhh[g];
        #pragma unroll
        for (int p = 0; p < 2; p++) {
            float2 fi = unpack2(accI2[q][p]);
            float2 fh = unpack2(accH2[q][p]);
            int b = b0 + 2 * p;
            g_gi[b * G3 + g]       = fi.x + bi;
            g_gi[(b + 1) * G3 + g] = fi.y + bi;
            g_gh[b * G3 + g]       = fh.x + bh;
            g_gh[(b + 1) * G3 + g] = fh.y + bh;
        }
    }
}

// ---------------- gate update + packed reset ----------------
__global__ void __launch_bounds__(256) gru_gate_kernel(int t, const float* __restrict__ seq_emb) {
    int id = blockIdx.x * 256 + threadIdx.x;   // 65536 threads
    int b = id >> 10, j = id & 1023;
    const float* hin = (t == 0) ? seq_emb : g_h;
    float ir = g_gi[b * G3 + j],        hr = g_gh[b * G3 + j];
    float iz = g_gi[b * G3 + 1024 + j], hz = g_gh[b * G3 + 1024 + j];
    float inn= g_gi[b * G3 + 2048 + j], hn = g_gh[b * G3 + 2048 + j];
    float r = 1.f / (1.f + expf(-(ir + hr)));
    float z = 1.f / (1.f + expf(-(iz + hz)));
    float n = tanhf(inn + r * hn);
    float h = (1.f - z) * n + z * hin[b * H + j];
    g_h[b * H + j] = h;
    if (id < B) g_packed[id] = 0ull;
}

// ---------------- logits GEMM + gumbel + argmax ----------------
// Grid 250 blocks x 256 threads. Block tile 64 b x 128 v; thread 8 b x 4 v.
// Mainloop uses packed f32x2 FMA, accumulators paired over batch.
__global__ void __launch_bounds__(256) logits_kernel(
    int t, const float* __restrict__ fcw, const float* __restrict__ fcb,
    float* __restrict__ out, uint32_t k0, uint32_t k1)
{
    __shared__ float sH[32][68];
    __shared__ float sW[32][132];
    int tid = threadIdx.x;
    int vblk = blockIdx.x * 128;
    int b0  = (tid >> 5) * 8;
    int v0l = (tid & 31) * 4;

    // acc2[v(4)][bpair(4)]: b = b0 + 2*p + {lo,hi}
    unsigned long long acc2[4][4];
    #pragma unroll
    for (int j = 0; j < 4; j++)
        #pragma unroll
        for (int p = 0; p < 4; p++) acc2[j][p] = 0ull;

    for (int c = 0; c < 32; c++) {
        int kb = c * 32;
        #pragma unroll
        for (int i = 0; i < 8; i++) {
            int e = tid + i * 256;
            int b = e >> 5, kk = e & 31;
            sH[kk][b] = g_h[b * H + kb + kk];
        }
        #pragma unroll
        for (int i = 0; i < 4; i++) {
            int e = tid + i * 256;
            int v = e >> 3, q = e & 7;
            float4 w = *(const float4*)&fcw[(size_t)(vblk + v) * H + kb + q * 4];
            sW[q * 4 + 0][v] = w.x; sW[q * 4 + 1][v] = w.y;
            sW[q * 4 + 2][v] = w.z; sW[q * 4 + 3][v] = w.w;
        }
        __syncthreads();
        #pragma unroll
        for (int kk = 0; kk < 32; kk++) {
            float4 w = *(const float4*)&sW[kk][v0l];
            ulonglong2 aA = *(const ulonglong2*)&sH[kk][b0];
            ulonglong2 aB = *(const ulonglong2*)&sH[kk][b0 + 4];
            unsigned long long w0 = pack2(w.x, w.x);
            unsigned long long w1 = pack2(w.y, w.y);
            unsigned long long w2 = pack2(w.z, w.z);
            unsigned long long w3 = pack2(w.w, w.w);
            fma2(acc2[0][0], aA.x, w0); fma2(acc2[0][1], aA.y, w0);
            fma2(acc2[0][2], aB.x, w0); fma2(acc2[0][3], aB.y, w0);
            fma2(acc2[1][0], aA.x, w1); fma2(acc2[1][1], aA.y, w1);
            fma2(acc2[1][2], aB.x, w1); fma2(acc2[1][3], aB.y, w1);
            fma2(acc2[2][0], aA.x, w2); fma2(acc2[2][1], aA.y, w2);
            fma2(acc2[2][2], aB.x, w2); fma2(acc2[2][3], aB.y, w2);
            fma2(acc2[3][0], aA.x, w3); fma2(acc2[3][1], aA.y, w3);
            fma2(acc2[3][2], aB.x, w3); fma2(acc2[3][3], aB.y, w3);
        }
        __syncthreads();
    }

    // Unpack to per-b rows
    float accF[8][4];
    #pragma unroll
    for (int j = 0; j < 4; j++) {
        #pragma unroll
        for (int p = 0; p < 4; p++) {
            float2 f = unpack2(acc2[j][p]);
            accF[2 * p][j]     = f.x;
            accF[2 * p + 1][j] = f.y;
        }
    }

    float4 bias = *(const float4*)&fcb[vblk + v0l];
    #pragma unroll
    for (int i = 0; i < 8; i++) {
        accF[i][0] += bias.x; accF[i][1] += bias.y;
        accF[i][2] += bias.z; accF[i][3] += bias.w;
    }

    float* outL = out + 3200 + (size_t)t * (B * V);
    #pragma unroll
    for (int i = 0; i < 8; i++) {
        int b = b0 + i;
        float4 st = make_float4(accF[i][0], accF[i][1], accF[i][2], accF[i][3]);
        *(float4*)&outL[(size_t)b * V + vblk + v0l] = st;
    }

    // Gumbel-max epilogue. JAX partitionable threefry: bits[i] = o0^o1 of tf(key, (0, i)), i = b*V+v.
    #pragma unroll
    for (int i = 0; i < 8; i++) {
        int b = b0 + i;
        unsigned long long p = 0ull;
        #pragma unroll
        for (int j = 0; j < 4; j++) {
            int vg = vblk + v0l + j;
            unsigned cnt = (unsigned)(b * V + vg);
            uint32_t o0, o1;
            tf2x32(k0, k1, 0u, cnt, o0, o1);
            uint32_t bits = o0 ^ o1;
            float f = __uint_as_float((bits >> 9) | 0x3f800000u) - 1.0f;
            float u = fmaxf(f, 1.17549435e-38f);
            float gmb = -logf(-logf(u));
            float val = accF[i][j] + gmb;
            unsigned s = __float_as_uint(val);
            unsigned ord = (s & 0x80000000u) ? ~s : (s | 0x80000000u);
            unsigned long long pj = ((unsigned long long)ord << 32)
                                  | (unsigned long long)(0x7FFFFFFFu - (unsigned)vg);
            if (pj > p) p = pj;
        }
        #pragma unroll
        for (int off = 16; off; off >>= 1) {
            unsigned long long q = __shfl_down_sync(0xFFFFFFFFu, p, off);
            if (q > p) p = q;
        }
        if ((tid & 31) == 0) atomicMax(&g_packed[b], p);
    }
}

// ---------------- final sample: packed -> index output (t = T-1 only) ----------------
__global__ void sample_kernel(int t, float* __restrict__ out) {
    int b = threadIdx.x;
    unsigned long long p = g_packed[b];
    int v = (int)(0x7FFFFFFFu - (unsigned)(p & 0xFFFFFFFFull));
    out[t * B + b] = (float)v;
}

// ---------------- launch ----------------
extern "C" void kernel_launch(void* const* d_in, const int* in_sizes, int n_in,
                              void* d_out, int out_size) {
    (void)in_sizes; (void)n_in; (void)out_size;
    const float* seq = (const float*)d_in[0];
    const float* emb = (const float*)d_in[1];
    const float* Wih = (const float*)d_in[2];
    const float* Whh = (const float*)d_in[3];
    const float* bih = (const float*)d_in[4];
    const float* bhh = (const float*)d_in[5];
    const float* fcw = (const float*)d_in[6];
    const float* fcb = (const float*)d_in[7];
    const int*   eos = (const int*)d_in[8];
    float* out = (float*)d_out;

    // keys: jax.random.split(key(42), 50), partitionable (fold-like):
    // key_t = threefry2x32((0,42), (0, t))
    uint32_t keys[T][2];
    for (int t = 0; t < T; t++) {
        uint32_t a, b;
        tf2x32_host(0u, 42u, 0u, (uint32_t)t, &a, &b);
        keys[t][0] = a; keys[t][1] = b;
    }

    for (int t = 0; t < T; t++) {
        gru_gemm_kernel<<<96, 256>>>(t, seq, emb, Wih, Whh, bih, bhh, eos, out);
        gru_gate_kernel<<<256, 256>>>(t, seq);
        logits_kernel<<<250, 256>>>(t, fcw, fcb, out, keys[t][0], keys[t][1]);
    }
    sample_kernel<<<1, 64>>>(T - 1, out);
}

// round 6
// speedup vs baseline: 1.0005x; 1.0005x over previous
#include <cuda_runtime.h>
#include <cstdint>

#define B 64
#define T 50
#define D 512
#define H 1024
#define V 32000
#define G3 3072   // 3*H

// ---------------- scratch (no allocations allowed) ----------------
__device__ float g_h[B * H];
__device__ float g_gi[B * G3];
__device__ float g_gh[B * G3];
__device__ unsigned long long g_packed[B];

// ---------------- packed f32x2 helpers (sm_100a) ----------------
__device__ __forceinline__ void fma2(unsigned long long& d, unsigned long long a, unsigned long long b) {
    asm("fma.rn.f32x2 %0, %1, %2, %0;" : "+l"(d) : "l"(a), "l"(b));
}
__device__ __forceinline__ unsigned long long pack2(float x, float y) {
    unsigned long long r; asm("mov.b64 %0, {%1, %2};" : "=l"(r) : "f"(x), "f"(y)); return r;
}
__device__ __forceinline__ float2 unpack2(unsigned long long v) {
    float2 r; asm("mov.b64 {%0, %1}, %2;" : "=f"(r.x), "=f"(r.y) : "l"(v)); return r;
}

// ---------------- threefry2x32 (exact JAX rotation/key schedule) ----------------
__device__ __forceinline__ void tf2x32(uint32_t k0, uint32_t k1, uint32_t x0, uint32_t x1,
                                       uint32_t& o0, uint32_t& o1) {
    uint32_t ks2 = k0 ^ k1 ^ 0x1BD11BDAu;
    x0 += k0; x1 += k1;
#define RND(r) { x0 += x1; x1 = __funnelshift_l(x1, x1, (r)); x1 ^= x0; }
    RND(13) RND(15) RND(26) RND(6)   x0 += k1;  x1 += ks2 + 1u;
    RND(17) RND(29) RND(16) RND(24)  x0 += ks2; x1 += k0  + 2u;
    RND(13) RND(15) RND(26) RND(6)   x0 += k0;  x1 += k1  + 3u;
    RND(17) RND(29) RND(16) RND(24)  x0 += k1;  x1 += ks2 + 4u;
    RND(13) RND(15) RND(26) RND(6)   x0 += ks2; x1 += k0  + 5u;
#undef RND
    o0 = x0; o1 = x1;
}

static inline uint32_t h_rotl(uint32_t v, int d) { return (v << d) | (v >> (32 - d)); }
static void tf2x32_host(uint32_t k0, uint32_t k1, uint32_t x0, uint32_t x1,
                        uint32_t* o0, uint32_t* o1) {
    uint32_t ks2 = k0 ^ k1 ^ 0x1BD11BDAu;
    const int rA[4] = {13, 15, 26, 6}, rB[4] = {17, 29, 16, 24};
    x0 += k0; x1 += k1;
    for (int i = 0; i < 4; i++) { x0 += x1; x1 = h_rotl(x1, rA[i]); x1 ^= x0; }
    x0 += k1;  x1 += ks2 + 1u;
    for (int i = 0; i < 4; i++) { x0 += x1; x1 = h_rotl(x1, rB[i]); x1 ^= x0; }
    x0 += ks2; x1 += k0 + 2u;
    for (int i = 0; i < 4; i++) { x0 += x1; x1 = h_rotl(x1, rA[i]); x1 ^= x0; }
    x0 += k0;  x1 += k1 + 3u;
    for (int i = 0; i < 4; i++) { x0 += x1; x1 = h_rotl(x1, rB[i]); x1 ^= x0; }
    x0 += k1;  x1 += ks2 + 4u;
    for (int i = 0; i < 4; i++) { x0 += x1; x1 = h_rotl(x1, rA[i]); x1 ^= x0; }
    x0 += ks2; x1 += k0 + 5u;
    *o0 = x0; *o1 = x1;
}

// ---------------- GRU gemm: gi = x@Wih^T + b_ih ; gh = h@Whh^T + b_hh ----------------
// Grid 96 blocks x 256 threads. Block tile: 64 b x 32 g rows, K = 512(x) + 1024(h).
// Also: block 0 writes out the sampled indices of step t-1 (read from g_packed).
__global__ void __launch_bounds__(256) gru_gemm_kernel(
    int t, const float* __restrict__ seq_emb, const float* __restrict__ emb,
    const float* __restrict__ Wih, const float* __restrict__ Whh,
    const float* __restrict__ bih, const float* __restrict__ bhh,
    const int* __restrict__ eosp, float* __restrict__ out)
{
    __shared__ float sA[64][68];
    __shared__ float sW[64][36];
    __shared__ int sIdx[B];
    int tid = threadIdx.x;
    int g0 = blockIdx.x * 32;

    if (tid < B) {
        int idx;
        if (t == 0) idx = eosp[0];
        else idx = (int)(0x7FFFFFFFu - (unsigned)(g_packed[tid] & 0xFFFFFFFFull));
        sIdx[tid] = idx;
        if (blockIdx.x == 0 && t > 0) out[(t - 1) * B + tid] = (float)idx;
    }
    __syncthreads();

    const float* hin = (t == 0) ? seq_emb : g_h;

    // acc pairs over batch: accI2[g(2)][bpair(2)], b = b0 + 2*p + {0,1}
    unsigned long long accI2[2][2] = {{0ull,0ull},{0ull,0ull}};
    unsigned long long accH2[2][2] = {{0ull,0ull},{0ull,0ull}};
    int gl0 = (tid & 15) * 2;
    int b0  = (tid >> 4) * 4;

    for (int c = 0; c < 24; c++) {
        int kb = c * 64;
        #pragma unroll
        for (int i = 0; i < 16; i++) {
            int e = tid + i * 256;
            int b = e >> 6, kk = e & 63;
            int kg = kb + kk;
            float v;
            if (kg < 512) v = emb[(size_t)sIdx[b] * D + kg];
            else          v = hin[b * H + (kg - 512)];
            sA[kk][b] = v;
        }
        #pragma unroll
        for (int i = 0; i < 8; i++) {
            int e = tid + i * 256;
            int gl = e >> 6, kk = e & 63;
            int g = g0 + gl;
            int kg = kb + kk;
            float v;
            if (kg < 512) v = Wih[(size_t)g * D + kg];
            else          v = Whh[(size_t)g * H + (kg - 512)];
            sW[kk][gl] = v;
        }
        __syncthreads();
        if (c < 8) {
            #pragma unroll
            for (int kk = 0; kk < 64; kk++) {
                ulonglong2 a2 = *(const ulonglong2*)&sA[kk][b0];
                float2 w = *(const float2*)&sW[kk][gl0];
                unsigned long long w0 = pack2(w.x, w.x);
                unsigned long long w1 = pack2(w.y, w.y);
                fma2(accI2[0][0], a2.x, w0); fma2(accI2[0][1], a2.y, w0);
                fma2(accI2[1][0], a2.x, w1); fma2(accI2[1][1], a2.y, w1);
            }
        } else {
            #pragma unroll
            for (int kk = 0; kk < 64; kk++) {
                ulonglong2 a2 = *(const ulonglong2*)&sA[kk][b0];
                float2 w = *(const float2*)&sW[kk][gl0];
                unsigned long long w0 = pack2(w.x, w.x);
                unsigned long long w1 = pack2(w.y, w.y);
                fma2(accH2[0][0], a2.x, w0); fma2(accH2[0][1], a2.y, w0);
                fma2(accH2[1][0], a2.x, w1); fma2(accH2[1][1], a2.y, w1);
            }
        }
        __syncthreads();
    }

    #pragma unroll
    for (int q = 0; q < 2; q++) {
        int g = g0 + gl0 + q;
        float bi = bih[g], bh = bhh[g];
        #pragma unroll
        for (int p = 0; p < 2; p++) {
            float2 fi = unpack2(accI2[q][p]);
            float2 fh = unpack2(accH2[q][p]);
            int b = b0 + 2 * p;
            g_gi[b * G3 + g]       = fi.x + bi;
            g_gi[(b + 1) * G3 + g] = fi.y + bi;
            g_gh[b * G3 + g]       = fh.x + bh;
            g_gh[(b + 1) * G3 + g] = fh.y + bh;
        }
    }
}

// ---------------- gate update + packed reset ----------------
__global__ void __launch_bounds__(256) gru_gate_kernel(int t, const float* __restrict__ seq_emb) {
    int id = blockIdx.x * 256 + threadIdx.x;   // 65536 threads
    int b = id >> 10, j = id & 1023;
    const float* hin = (t == 0) ? seq_emb : g_h;
    float ir = g_gi[b * G3 + j],        hr = g_gh[b * G3 + j];
    float iz = g_gi[b * G3 + 1024 + j], hz = g_gh[b * G3 + 1024 + j];
    float inn= g_gi[b * G3 + 2048 + j], hn = g_gh[b * G3 + 2048 + j];
    float r = 1.f / (1.f + expf(-(ir + hr)));
    float z = 1.f / (1.f + expf(-(iz + hz)));
    float n = tanhf(inn + r * hn);
    float h = (1.f - z) * n + z * hin[b * H + j];
    g_h[b * H + j] = h;
    if (id < B) g_packed[id] = 0ull;
}

// ---------------- logits GEMM + gumbel + argmax ----------------
// Grid 250 blocks x 256 threads. Block tile 64 b x 128 v; thread 8 b x 4 v.
// Mainloop uses packed f32x2 FMA, accumulators paired over batch.
__global__ void __launch_bounds__(256) logits_kernel(
    int t, const float* __restrict__ fcw, const float* __restrict__ fcb,
    float* __restrict__ out, uint32_t k0, uint32_t k1)
{
    __shared__ float sH[32][68];
    __shared__ float sW[32][132];
    int tid = threadIdx.x;
    int vblk = blockIdx.x * 128;
    int b0  = (tid >> 5) * 8;
    int v0l = (tid & 31) * 4;

    // acc2[v(4)][bpair(4)]: b = b0 + 2*p + {lo,hi}
    unsigned long long acc2[4][4];
    #pragma unroll
    for (int j = 0; j < 4; j++)
        #pragma unroll
        for (int p = 0; p < 4; p++) acc2[j][p] = 0ull;

    for (int c = 0; c < 32; c++) {
        int kb = c * 32;
        #pragma unroll
        for (int i = 0; i < 8; i++) {
            int e = tid + i * 256;
            int b = e >> 5, kk = e & 31;
            sH[kk][b] = g_h[b * H + kb + kk];
        }
        #pragma unroll
        for (int i = 0; i < 4; i++) {
            int e = tid + i * 256;
            int v = e >> 3, q = e & 7;
            float4 w = *(const float4*)&fcw[(size_t)(vblk + v) * H + kb + q * 4];
            sW[q * 4 + 0][v] = w.x; sW[q * 4 + 1][v] = w.y;
            sW[q * 4 + 2][v] = w.z; sW[q * 4 + 3][v] = w.w;
        }
        __syncthreads();
        #pragma unroll
        for (int kk = 0; kk < 32; kk++) {
            float4 w = *(const float4*)&sW[kk][v0l];
            ulonglong2 aA = *(const ulonglong2*)&sH[kk][b0];
            ulonglong2 aB = *(const ulonglong2*)&sH[kk][b0 + 4];
            unsigned long long w0 = pack2(w.x, w.x);
            unsigned long long w1 = pack2(w.y, w.y);
            unsigned long long w2 = pack2(w.z, w.z);
            unsigned long long w3 = pack2(w.w, w.w);
            fma2(acc2[0][0], aA.x, w0); fma2(acc2[0][1], aA.y, w0);
            fma2(acc2[0][2], aB.x, w0); fma2(acc2[0][3], aB.y, w0);
            fma2(acc2[1][0], aA.x, w1); fma2(acc2[1][1], aA.y, w1);
            fma2(acc2[1][2], aB.x, w1); fma2(acc2[1][3], aB.y, w1);
            fma2(acc2[2][0], aA.x, w2); fma2(acc2[2][1], aA.y, w2);
            fma2(acc2[2][2], aB.x, w2); fma2(acc2[2][3], aB.y, w2);
            fma2(acc2[3][0], aA.x, w3); fma2(acc2[3][1], aA.y, w3);
            fma2(acc2[3][2], aB.x, w3); fma2(acc2[3][3], aB.y, w3);
        }
        __syncthreads();
    }

    // Unpack to per-b rows
    float accF[8][4];
    #pragma unroll
    for (int j = 0; j < 4; j++) {
        #pragma unroll
        for (int p = 0; p < 4; p++) {
            float2 f = unpack2(acc2[j][p]);
            accF[2 * p][j]     = f.x;
            accF[2 * p + 1][j] = f.y;
        }
    }

    float4 bias = *(const float4*)&fcb[vblk + v0l];
    #pragma unroll
    for (int i = 0; i < 8; i++) {
        accF[i][0] += bias.x; accF[i][1] += bias.y;
        accF[i][2] += bias.z; accF[i][3] += bias.w;
    }

    float* outL = out + 3200 + (size_t)t * (B * V);
    #pragma unroll
    for (int i = 0; i < 8; i++) {
        int b = b0 + i;
        float4 st = make_float4(accF[i][0], accF[i][1], accF[i][2], accF[i][3]);
        *(float4*)&outL[(size_t)b * V + vblk + v0l] = st;
    }

    // Gumbel-max epilogue. JAX partitionable threefry: bits[i] = o0^o1 of tf(key, (0, i)), i = b*V+v.
    #pragma unroll
    for (int i = 0; i < 8; i++) {
        int b = b0 + i;
        unsigned long long p = 0ull;
        #pragma unroll
        for (int j = 0; j < 4; j++) {
            int vg = vblk + v0l + j;
            unsigned cnt = (unsigned)(b * V + vg);
            uint32_t o0, o1;
            tf2x32(k0, k1, 0u, cnt, o0, o1);
            uint32_t bits = o0 ^ o1;
            float f = __uint_as_float((bits >> 9) | 0x3f800000u) - 1.0f;
            float u = fmaxf(f, 1.17549435e-38f);
            float gmb = -logf(-logf(u));
            float val = accF[i][j] + gmb;
            unsigned s = __float_as_uint(val);
            unsigned ord = (s & 0x80000000u) ? ~s : (s | 0x80000000u);
            unsigned long long pj = ((unsigned long long)ord << 32)
                                  | (unsigned long long)(0x7FFFFFFFu - (unsigned)vg);
            if (pj > p) p = pj;
        }
        #pragma unroll
        for (int off = 16; off; off >>= 1) {
            unsigned long long q = __shfl_down_sync(0xFFFFFFFFu, p, off);
            if (q > p) p = q;
        }
        if ((tid & 31) == 0) atomicMax(&g_packed[b], p);
    }
}

// ---------------- final sample: packed -> index output (t = T-1 only) ----------------
__global__ void sample_kernel(int t, float* __restrict__ out) {
    int b = threadIdx.x;
    unsigned long long p = g_packed[b];
    int v = (int)(0x7FFFFFFFu - (unsigned)(p & 0xFFFFFFFFull));
    out[t * B + b] = (float)v;
}

// ---------------- launch ----------------
extern "C" void kernel_launch(void* const* d_in, const int* in_sizes, int n_in,
                              void* d_out, int out_size) {
    (void)in_sizes; (void)n_in; (void)out_size;
    const float* seq = (const float*)d_in[0];
    const float* emb = (const float*)d_in[1];
    const float* Wih = (const float*)d_in[2];
    const float* Whh = (const float*)d_in[3];
    const float* bih = (const float*)d_in[4];
    const float* bhh = (const float*)d_in[5];
    const float* fcw = (const float*)d_in[6];
    const float* fcb = (const float*)d_in[7];
    const int*   eos = (const int*)d_in[8];
    float* out = (float*)d_out;

    // keys: jax.random.split(key(42), 50), partitionable (fold-like):
    // key_t = threefry2x32((0,42), (0, t))
    uint32_t keys[T][2];
    for (int t = 0; t < T; t++) {
        uint32_t a, b;
        tf2x32_host(0u, 42u, 0u, (uint32_t)t, &a, &b);
        keys[t][0] = a; keys[t][1] = b;
    }

    for (int t = 0; t < T; t++) {
        gru_gemm_kernel<<<96, 256>>>(t, seq, emb, Wih, Whh, bih, bhh, eos, out);
        gru_gate_kernel<<<256, 256>>>(t, seq);
        logits_kernel<<<250, 256>>>(t, fcw, fcb, out, keys[t][0], keys[t][1]);
    }
    sample_kernel<<<1, 64>>>(T - 1, out);
}